// round 17
// baseline (speedup 1.0000x reference)
#include <cuda_runtime.h>
#include <cuda_fp16.h>
#include <cstdint>
#include <math_constants.h>

// Problem shapes (fixed by the dataset)
#define NQ 2048
#define NS 65536
#define KF 512          // feature dim = 32*16
#define KSEL 16         // top-k
#define NCAND 512       // candidate cap (expected ~90 per query at Z=3)
#define ZTHRESH 3.0f    // candidate threshold z-score (rank ~88 of 65536)
#define NOISE_MARGIN 2.0f  // f16 screen noise (~6 sigma)

// GEMM tiling: CTA 128(M) x 256(N) x BK=32, 3-stage cp.async pipeline
#define BM 128
#define BN 256
#define BK 32
#define NSLABS (KF / BK)                 // 16
#define STAGES 3
#define STAGE_A_BYTES (BM * BK * 2)      // 8192
#define STAGE_B_BYTES (BN * BK * 2)      // 16384
#define STAGE_BYTES (STAGE_A_BYTES + STAGE_B_BYTES)   // 24576
#define GEMM_DYN_SMEM (STAGES * STAGE_BYTES)          // 73728

// Scratch (no cudaMalloc allowed anywhere). No d2 matrix.
__device__ float  g_q2[NQ];                // exact fp32 norms
__device__ float  g_s2[NS];
__device__ float  g_stats[2];              // [0]=mean(s2), [1]=var(s2)
__device__ int    g_cand[(size_t)NQ * NCAND];
__device__ int    g_ccount[NQ];
__device__ __half g_qh[(size_t)NQ * KF];   // f16 inputs for the screen GEMM
__device__ __half g_sh[(size_t)NS * KF];

// ---------------------------------------------------------------------------
// helpers
// ---------------------------------------------------------------------------
__device__ __forceinline__ uint32_t smem_u32(const void* p) {
    uint32_t a;
    asm("{ .reg .u64 t; cvta.to.shared.u64 t, %1; cvt.u32.u64 %0, t; }"
        : "=r"(a) : "l"(p));
    return a;
}
__device__ __forceinline__ void cp16(uint32_t dst, const void* src) {
    asm volatile("cp.async.cg.shared.global [%0], [%1], 16;"
                 :: "r"(dst), "l"(src));
}
__device__ __forceinline__ void ldsm_x4(uint32_t addr, uint32_t& r0, uint32_t& r1,
                                        uint32_t& r2, uint32_t& r3) {
    asm volatile("ldmatrix.sync.aligned.m8n8.x4.shared.b16 {%0,%1,%2,%3}, [%4];"
                 : "=r"(r0), "=r"(r1), "=r"(r2), "=r"(r3) : "r"(addr));
}

// ---------------------------------------------------------------------------
// Kernel 1: fused exact fp32 norms + fp32->f16 conversion. One warp per row.
// ---------------------------------------------------------------------------
__global__ void norms_kernel(const float* __restrict__ q,
                             const float* __restrict__ s) {
    int gw   = (blockIdx.x * blockDim.x + threadIdx.x) >> 5;
    int lane = threadIdx.x & 31;
    if (gw >= NQ + NS) return;
    const bool isQ = (gw < NQ);
    const int row  = isQ ? gw : gw - NQ;
    const float* base = isQ ? (q + (size_t)row * KF) : (s + (size_t)row * KF);
    uint2* dsth = isQ ? (uint2*)(g_qh + (size_t)row * KF)
                      : (uint2*)(g_sh + (size_t)row * KF);
    const float4* b4 = (const float4*)base;

    float fs = 0.f;
    #pragma unroll
    for (int c = 0; c < 4; c++) {
        float4 v = b4[c * 32 + lane];
        fs += v.x * v.x + v.y * v.y + v.z * v.z + v.w * v.w;
        __half2 lo = __float22half2_rn(make_float2(v.x, v.y));
        __half2 hi = __float22half2_rn(make_float2(v.z, v.w));
        uint2 u;
        u.x = *reinterpret_cast<uint32_t*>(&lo);
        u.y = *reinterpret_cast<uint32_t*>(&hi);
        dsth[c * 32 + lane] = u;
    }
    #pragma unroll
    for (int o = 16; o; o >>= 1) fs += __shfl_down_sync(0xffffffffu, fs, o);
    if (lane == 0) {
        if (isQ) g_q2[row] = fs;
        else     g_s2[row] = fs;
    }
}

// ---------------------------------------------------------------------------
// Kernel 1b: empirical mean/variance of s2 (single block) + zero counters.
// ---------------------------------------------------------------------------
__global__ __launch_bounds__(1024)
void stats_zero_kernel() {
    __shared__ float red[1024];
    const int tid = threadIdx.x;
    g_ccount[tid] = 0;
    g_ccount[tid + 1024] = 0;

    float sum = 0.f;
    for (int i = tid; i < NS; i += 1024) sum += g_s2[i];
    red[tid] = sum;
    __syncthreads();
    #pragma unroll
    for (int st = 512; st > 0; st >>= 1) {
        if (tid < st) red[tid] += red[tid + st];
        __syncthreads();
    }
    const float mu = red[0] / (float)NS;
    __syncthreads();

    float vs = 0.f;
    for (int i = tid; i < NS; i += 1024) {
        float d = g_s2[i] - mu;
        vs += d * d;
    }
    red[tid] = vs;
    __syncthreads();
    #pragma unroll
    for (int st = 512; st > 0; st >>= 1) {
        if (tid < st) red[tid] += red[tid + st];
        __syncthreads();
    }
    if (tid == 0) {
        g_stats[0] = mu;
        g_stats[1] = red[0] / (float)NS;
    }
}

// ---------------------------------------------------------------------------
// Kernel 2: full-dim f16 screen GEMM with FUSED candidate selection.
// CTA 128x256, warp tile 64x64 (8 warps), f16-accum mma.sync, cp.async
// 3-stage, ldmatrix. Epilogue: analytic per-row threshold -> atomic append.
// grid = (NQ/BM, NS/BN) = (16, 256), M fast -> B-tile L2 reuse.
// ---------------------------------------------------------------------------
__global__ __launch_bounds__(256)
void dist_gemm() {
    extern __shared__ __align__(16) char dynsmem[];
    const uint32_t sbase = smem_u32(dynsmem);

    const int tid  = threadIdx.x;
    const int wid  = tid >> 5;
    const int lane = tid & 31;
    const int m0 = blockIdx.x * BM;
    const int n0 = blockIdx.y * BN;
    const int wm = (wid & 1) * 64;        // warp tile 64(M) x 64(N)
    const int wn = (wid >> 1) * 64;

    // cp.async staging: A = 512 chunks (2/thread), B = 1024 chunks (4/thread)
    int aIdx0 = tid, aIdx1 = tid + 256;
    int ar0 = aIdx0 >> 2, ac0 = aIdx0 & 3;
    int ar1 = aIdx1 >> 2, ac1 = aIdx1 & 3;
    uint32_t dA0 = ar0 * 64 + ((ac0 ^ ((ar0 >> 1) & 3)) << 4);
    uint32_t dA1 = ar1 * 64 + ((ac1 ^ ((ar1 >> 1) & 3)) << 4);
    int br_[4], bc_[4];
    uint32_t dB[4];
    #pragma unroll
    for (int it = 0; it < 4; it++) {
        int idx = tid + it * 256;          // 0..1023
        br_[it] = idx >> 2;                // row 0..255
        bc_[it] = idx & 3;
        dB[it] = br_[it] * 64 + ((bc_[it] ^ ((br_[it] >> 1) & 3)) << 4);
    }

    const __half* Ag = g_qh + (size_t)m0 * KF;
    const __half* Bg = g_sh + (size_t)n0 * KF;

    auto issue = [&](int stage, int kt) {
        uint32_t sA = sbase + stage * STAGE_BYTES;
        uint32_t sB = sA + STAGE_A_BYTES;
        cp16(sA + dA0, Ag + (size_t)ar0 * KF + kt * BK + ac0 * 8);
        cp16(sA + dA1, Ag + (size_t)ar1 * KF + kt * BK + ac1 * 8);
        #pragma unroll
        for (int it = 0; it < 4; it++)
            cp16(sB + dB[it], Bg + (size_t)br_[it] * KF + kt * BK + bc_[it] * 8);
        asm volatile("cp.async.commit_group;" ::: "memory");
    };

    // f16 accumulators: 2 packed regs per 16x8 mma tile; 4(m) x 8(n) tiles
    uint32_t acc[4][8][2];
    #pragma unroll
    for (int mt = 0; mt < 4; mt++)
        #pragma unroll
        for (int nt = 0; nt < 8; nt++) { acc[mt][nt][0] = 0u; acc[mt][nt][1] = 0u; }

    const int frow = lane & 15;
    const int fch  = lane >> 4;

    issue(0, 0);
    issue(1, 1);

    #pragma unroll 1
    for (int kt = 0; kt < NSLABS; kt++) {
        if (kt + 2 < NSLABS) issue((kt + 2) % STAGES, kt + 2);
        if (kt < NSLABS - 2)
            asm volatile("cp.async.wait_group 2;" ::: "memory");
        else if (kt == NSLABS - 2)
            asm volatile("cp.async.wait_group 1;" ::: "memory");
        else
            asm volatile("cp.async.wait_group 0;" ::: "memory");
        __syncthreads();

        const uint32_t sA = sbase + (kt % STAGES) * STAGE_BYTES;
        const uint32_t sB = sA + STAGE_A_BYTES;

        #pragma unroll
        for (int ks = 0; ks < 2; ks++) {
            uint32_t afr[4][4], br[4][4];
            const int ch = ks * 2 + fch;
            #pragma unroll
            for (int mt = 0; mt < 4; mt++) {
                int r = wm + mt * 16 + frow;
                uint32_t addr = sA + r * 64 + ((ch ^ ((r >> 1) & 3)) << 4);
                ldsm_x4(addr, afr[mt][0], afr[mt][1], afr[mt][2], afr[mt][3]);
            }
            #pragma unroll
            for (int g = 0; g < 4; g++) {
                int r = wn + g * 16 + frow;
                uint32_t addr = sB + r * 64 + ((ch ^ ((r >> 1) & 3)) << 4);
                ldsm_x4(addr, br[g][0], br[g][1], br[g][2], br[g][3]);
            }
            #pragma unroll
            for (int mt = 0; mt < 4; mt++)
                #pragma unroll
                for (int nt = 0; nt < 8; nt++) {
                    const int g = nt >> 1, h = nt & 1;
                    asm volatile(
                        "mma.sync.aligned.m16n8k16.row.col.f16.f16.f16.f16 "
                        "{%0,%1}, {%2,%3,%4,%5}, {%6,%7}, {%0,%1};\n"
                        : "+r"(acc[mt][nt][0]), "+r"(acc[mt][nt][1])
                        : "r"(afr[mt][0]), "r"(afr[mt][1]),
                          "r"(afr[mt][2]), "r"(afr[mt][3]),
                          "r"(br[g][h]), "r"(br[g][h + 2]));
                }
        }
        __syncthreads();
    }

    // fused epilogue: threshold + candidate append (no d2 write)
    const float mu  = g_stats[0];
    const float var = g_stats[1];
    const float vdim = mu / (float)KF;    // empirical per-dim variance of s

    #pragma unroll
    for (int mt = 0; mt < 4; mt++) {
        int rlo = m0 + wm + mt * 16 + (lane >> 2);
        int rhi = rlo + 8;
        float q2lo = g_q2[rlo];
        float q2hi = g_q2[rhi];
        float Tlo = q2lo + mu - ZTHRESH * sqrtf(var + 4.f * q2lo * vdim) + NOISE_MARGIN;
        float Thi = q2hi + mu - ZTHRESH * sqrtf(var + 4.f * q2hi * vdim) + NOISE_MARGIN;
        #pragma unroll
        for (int nt = 0; nt < 8; nt++) {
            int nc = n0 + wn + nt * 8 + (lane & 3) * 2;
            float s20 = g_s2[nc], s21 = g_s2[nc + 1];
            __half2 h0 = *reinterpret_cast<__half2*>(&acc[mt][nt][0]);
            __half2 h1 = *reinterpret_cast<__half2*>(&acc[mt][nt][1]);
            float d00 = q2lo + s20 - 2.f * __low2float(h0);
            float d01 = q2lo + s21 - 2.f * __high2float(h0);
            float d10 = q2hi + s20 - 2.f * __low2float(h1);
            float d11 = q2hi + s21 - 2.f * __high2float(h1);
            if (d00 <= Tlo) {
                int sl = atomicAdd(&g_ccount[rlo], 1);
                if (sl < NCAND) g_cand[(size_t)rlo * NCAND + sl] = nc;
            }
            if (d01 <= Tlo) {
                int sl = atomicAdd(&g_ccount[rlo], 1);
                if (sl < NCAND) g_cand[(size_t)rlo * NCAND + sl] = nc + 1;
            }
            if (d10 <= Thi) {
                int sl = atomicAdd(&g_ccount[rhi], 1);
                if (sl < NCAND) g_cand[(size_t)rhi * NCAND + sl] = nc;
            }
            if (d11 <= Thi) {
                int sl = atomicAdd(&g_ccount[rhi], 1);
                if (sl < NCAND) g_cand[(size_t)rhi * NCAND + sl] = nc + 1;
            }
        }
    }
}

// ---------------------------------------------------------------------------
// Kernel 3: exact fp32 refinement over up to NCAND candidates + weights.
// Two candidates per warp-iteration (independent dot chains), then 16
// rounds of lexicographic argmin over the 512-slot shared array.
// Output layout (float32): [ indices (NQ*16) | weights (NQ*16) ]
// ---------------------------------------------------------------------------
__global__ __launch_bounds__(256)
void refine_kernel(const float* __restrict__ q,
                   const float* __restrict__ s,
                   float* __restrict__ out) {
    const int qrow = blockIdx.x;
    const int tid  = threadIdx.x;
    const int warp = tid >> 5;
    const int lane = tid & 31;

    __shared__ float qs[KF];
    __shared__ float ev[NCAND];
    __shared__ int   ei[NCAND];
    __shared__ float sv[256];
    __shared__ int   si[256];
    __shared__ float resv[KSEL];
    __shared__ int   resi[KSEL];

    int m = g_ccount[qrow];
    if (m > NCAND) m = NCAND;

    for (int i = tid; i < KF; i += 256) qs[i] = q[(size_t)qrow * KF + i];
    for (int i = tid; i < NCAND; i += 256) { ev[i] = CUDART_INF_F; ei[i] = 0x7fffffff; }
    __syncthreads();

    const float4* qs4 = (const float4*)qs;
    const float q2v = g_q2[qrow];
    // two candidates per iteration, 8 warps -> stride 16
    for (int ci = warp * 2; ci < m; ci += 16) {
        int  s0 = g_cand[(size_t)qrow * NCAND + ci];
        bool have1 = (ci + 1 < m);
        int  s1 = have1 ? g_cand[(size_t)qrow * NCAND + ci + 1] : s0;
        const float4* r0 = (const float4*)(s + (size_t)s0 * KF);
        const float4* r1 = (const float4*)(s + (size_t)s1 * KF);
        float d0 = 0.f, d1 = 0.f;
        #pragma unroll
        for (int t = 0; t < 4; t++) {
            float4 u = qs4[t * 32 + lane];
            float4 v0 = r0[t * 32 + lane];
            float4 v1 = r1[t * 32 + lane];
            d0 += v0.x * u.x + v0.y * u.y + v0.z * u.z + v0.w * u.w;
            d1 += v1.x * u.x + v1.y * u.y + v1.z * u.z + v1.w * u.w;
        }
        #pragma unroll
        for (int o = 16; o; o >>= 1) {
            d0 += __shfl_down_sync(0xffffffffu, d0, o);
            d1 += __shfl_down_sync(0xffffffffu, d1, o);
        }
        if (lane == 0) {
            ev[ci] = q2v + g_s2[s0] - 2.f * d0;
            ei[ci] = s0;
            if (have1) {
                ev[ci + 1] = q2v + g_s2[s1] - 2.f * d1;
                ei[ci + 1] = s1;
            }
        }
    }
    __syncthreads();

    for (int r = 0; r < KSEL; r++) {
        float v1 = ev[tid];       int i1 = ei[tid];
        float v2 = ev[tid + 256]; int i2 = ei[tid + 256];
        if (v2 < v1 || (v2 == v1 && i2 < i1)) { v1 = v2; i1 = i2; }
        sv[tid] = v1; si[tid] = i1;
        __syncthreads();
        #pragma unroll
        for (int st = 128; st > 0; st >>= 1) {
            if (tid < st) {
                float vv = sv[tid + st]; int ii = si[tid + st];
                if (vv < sv[tid] || (vv == sv[tid] && ii < si[tid])) {
                    sv[tid] = vv; si[tid] = ii;
                }
            }
            __syncthreads();
        }
        int winIdx = si[0];
        if (tid == 0) { resv[r] = sv[0]; resi[r] = winIdx; }
        __syncthreads();
        if (ei[tid] == winIdx)       ev[tid] = CUDART_INF_F;
        if (ei[tid + 256] == winIdx) ev[tid + 256] = CUDART_INF_F;
        __syncthreads();
    }

    if (tid == 0) {
        float w[KSEL];
        float ssum = 0.f;
        #pragma unroll
        for (int r = 0; r < KSEL; r++) {
            float d = sqrtf(fmaxf(resv[r], 1e-12f));
            w[r] = 1.f / (d + 1e-6f);
            ssum += w[r];
        }
        float inv = 1.f / ssum;
        #pragma unroll
        for (int r = 0; r < KSEL; r++) {
            out[(size_t)qrow * KSEL + r] = (float)resi[r];
            out[(size_t)NQ * KSEL + (size_t)qrow * KSEL + r] = w[r] * inv;
        }
    }
}

// ---------------------------------------------------------------------------
extern "C" void kernel_launch(void* const* d_in, const int* in_sizes, int n_in,
                              void* d_out, int out_size) {
    const float* q = (const float*)d_in[0];  // (2048, 32, 16) -> (2048, 512)
    const float* s = (const float*)d_in[1];  // (65536, 32, 16) -> (65536, 512)
    float* out = (float*)d_out;

    static bool attr_done = false;
    if (!attr_done) {
        cudaFuncSetAttribute(dist_gemm,
                             cudaFuncAttributeMaxDynamicSharedMemorySize,
                             GEMM_DYN_SMEM);
        attr_done = true;
    }

    // 1) fused exact fp32 norms + fp32->f16 conversion
    int rows = NQ + NS;
    int nblocks = (rows * 32 + 255) / 256;
    norms_kernel<<<nblocks, 256>>>(q, s);

    // 1b) empirical s2 statistics + zero candidate counters
    stats_zero_kernel<<<1, 1024>>>();

    // 2) full-dim f16 screen GEMM with fused candidate selection
    dim3 g(NQ / BM, NS / BN);
    dist_gemm<<<g, 256, GEMM_DYN_SMEM>>>();

    // 3) exact fp32 refinement + output
    refine_kernel<<<NQ, 256>>>(q, s, out);
}